// round 1
// baseline (speedup 1.0000x reference)
#include <cuda_runtime.h>
#include <cstdint>

#define NB      64
#define DMODEL  2048
#define DSSM    4096
#define NHEADS  64
#define HEADDIM 64
#define DSTATE  128
#define DINPROJ 8512   // 2*4096 + 2*128 + 64

// ---------------- scratch (device globals; no allocation) ----------------
__device__ __align__(16) int   g_xq [NB*512];        // hidden quantized, packed int8x4
__device__            float    g_xs [NB];
__device__ __align__(16) int   g_wq1[DINPROJ*512];   // W_in  quantized (17.4 MB)
__device__            float    g_ws1[DINPROJ];
__device__ __align__(16) float g_zx [NB*DINPROJ];    // zxbcdt fp32
__device__ __align__(16) float g_xfq[NB*DSSM];       // fake-quanted x
__device__ __align__(16) float g_Bq [NB*DSTATE];
__device__ __align__(16) float g_Cq [NB*DSTATE];
__device__            float    g_dtv[NB*NHEADS];
__device__            float    g_scl[NB*NHEADS];
__device__            float    g_bcd[NB];
__device__ __align__(16) float g_yraw[NB*DSSM];
__device__ __align__(16) int   g_yq [NB*1024];       // y quantized, packed
__device__            float    g_ys [NB];
__device__ __align__(16) int   g_wq2[DMODEL*1024];   // W_out quantized (8.4 MB)
__device__            float    g_ws2[DMODEL];

// ---------------- helpers ----------------
__device__ __forceinline__ int pack4(float a, float b, float c, float d, float s) {
    int q0 = (int)rintf(a / s);
    int q1 = (int)rintf(b / s);
    int q2 = (int)rintf(c / s);
    int q3 = (int)rintf(d / s);
    return (q0 & 0xFF) | ((q1 & 0xFF) << 8) | ((q2 & 0xFF) << 16) | (q3 << 24);
}

__device__ __forceinline__ float warpMax(float v) {
    #pragma unroll
    for (int o = 16; o; o >>= 1) v = fmaxf(v, __shfl_xor_sync(0xFFFFFFFFu, v, o));
    return v;
}

// ---------------- K0: quantize hidden states ----------------
__global__ void quant_x_kernel(const float* __restrict__ hs) {
    __shared__ float sh[256];
    int b = blockIdx.x, t = threadIdx.x;
    const float* row = hs + b * DMODEL;
    float m = 0.f;
    for (int i = t; i < DMODEL; i += 256) m = fmaxf(m, fabsf(row[i]));
    sh[t] = m; __syncthreads();
    for (int s = 128; s > 0; s >>= 1) { if (t < s) sh[t] = fmaxf(sh[t], sh[t + s]); __syncthreads(); }
    float sc = sh[0] / 127.0f;
    if (sc == 0.f) sc = 1.f;
    if (t == 0) g_xs[b] = sc;
    const float4* row4 = (const float4*)row;
    for (int k4 = t; k4 < 512; k4 += 256) {
        float4 v = row4[k4];
        g_xq[b * 512 + k4] = pack4(v.x, v.y, v.z, v.w, sc);
    }
}

// ---------------- W quantization (row-per-warp, two passes, coalesced) ----------------
template<int KJ>   // K = KJ*128 elements per row; K4 = KJ*32
__global__ void quant_w_kernel(const float* __restrict__ W, int* __restrict__ wq,
                               float* __restrict__ ws) {
    int warp = threadIdx.x >> 5, lane = threadIdx.x & 31;
    int row  = blockIdx.x * 8 + warp;
    const float4* Wr = (const float4*)(W + (size_t)row * (KJ * 128));
    float m = 0.f;
    #pragma unroll
    for (int j = 0; j < KJ; j++) {
        float4 v = Wr[j * 32 + lane];
        m = fmaxf(m, fmaxf(fmaxf(fabsf(v.x), fabsf(v.y)), fmaxf(fabsf(v.z), fabsf(v.w))));
    }
    m = warpMax(m);
    float s = m / 127.0f;
    if (s == 0.f) s = 1.f;
    if (lane == 0) ws[row] = s;
    int* out = wq + (size_t)row * (KJ * 32);
    #pragma unroll
    for (int j = 0; j < KJ; j++) {
        float4 v = Wr[j * 32 + lane];                 // L1-hit reload
        out[j * 32 + lane] = pack4(v.x, v.y, v.z, v.w, s);
    }
}

// ---------------- int8 dp4a GEMM: out[b*M + row] = isum * ws[row] * xs[b] ----------------
template<int ROWS, int KJ>
__global__ void __launch_bounds__(128)
gemm_kernel(const int* __restrict__ wq, const float* __restrict__ ws,
            const int* __restrict__ xq, const float* __restrict__ xs,
            float* __restrict__ out, int M) {
    int warp = threadIdx.x >> 5, lane = threadIdx.x & 31;
    int nw   = blockDim.x >> 5;
    int base = (blockIdx.x * nw + warp) * ROWS;
    const int K4 = KJ * 32;

    int   w[ROWS][KJ];
    float wsv[ROWS];
    #pragma unroll
    for (int r = 0; r < ROWS; r++) {
        const int* wr = wq + (size_t)(base + r) * K4;
        #pragma unroll
        for (int j = 0; j < KJ; j++) w[r][j] = wr[j * 32 + lane];
        wsv[r] = ws[base + r];
    }

    #pragma unroll 1
    for (int b = 0; b < NB; b++) {
        const int* xb = xq + b * K4;
        int acc[ROWS];
        #pragma unroll
        for (int r = 0; r < ROWS; r++) acc[r] = 0;
        #pragma unroll
        for (int j = 0; j < KJ; j++) {
            int xv = xb[j * 32 + lane];
            #pragma unroll
            for (int r = 0; r < ROWS; r++) acc[r] = __dp4a(w[r][j], xv, acc[r]);
        }
        int red[ROWS];
        #pragma unroll
        for (int r = 0; r < ROWS; r++) red[r] = __reduce_add_sync(0xFFFFFFFFu, acc[r]);
        if (lane < ROWS) {
            int   sv = 0;
            float wv = 0.f;
            #pragma unroll
            for (int r = 0; r < ROWS; r++) if (lane == r) { sv = red[r]; wv = wsv[r]; }
            out[b * M + base + lane] = (float)sv * (wv * xs[b]);
        }
    }
}

// ---------------- K2: xBC fake-quant, B·C dot, dt/softplus/exp ----------------
__global__ void k2_kernel(const float* __restrict__ dt_bias, const float* __restrict__ A_log) {
    __shared__ float sh[256];
    __shared__ float s_scale;
    int b = blockIdx.x, t = threadIdx.x;
    const float* xbc = g_zx + b * DINPROJ + DSSM;   // 4352 elements
    float m = 0.f;
    for (int i = t; i < 4352; i += 256) m = fmaxf(m, fabsf(xbc[i]));
    sh[t] = m; __syncthreads();
    for (int s = 128; s > 0; s >>= 1) { if (t < s) sh[t] = fmaxf(sh[t], sh[t + s]); __syncthreads(); }
    if (t == 0) { float sc = sh[0] / 127.0f; s_scale = (sc == 0.f) ? 1.f : sc; }
    __syncthreads();
    float sc = s_scale;
    for (int i = t; i < 4352; i += 256) {
        float fq = rintf(xbc[i] / sc) * sc;
        if (i < DSSM)               g_xfq[b * DSSM + i] = fq;
        else if (i < DSSM + DSTATE) g_Bq[b * DSTATE + (i - DSSM)] = fq;
        else                        g_Cq[b * DSTATE + (i - DSSM - DSTATE)] = fq;
    }
    __syncthreads();
    float p = 0.f;
    if (t < DSTATE) p = g_Bq[b * DSTATE + t] * g_Cq[b * DSTATE + t];
    sh[t] = p; __syncthreads();
    for (int s = 128; s > 0; s >>= 1) { if (t < s) sh[t] += sh[t + s]; __syncthreads(); }
    if (t == 0) g_bcd[b] = sh[0];

    if (t < NHEADS) {
        float dtr = g_zx[b * DINPROJ + (2 * DSSM + 2 * DSTATE) + t] + dt_bias[t];
        float dts;
        if (dtr < -2.0f)      dts = 0.0f;
        else if (dtr > 2.0f)  dts = dtr;
        else                  dts = 0.69314718055994531f + 0.5f * dtr
                                    + (dtr * dtr) / 8.0f + (dtr * dtr * dtr) / 48.0f;
        float A  = -expf(A_log[t]);
        float x  = fmaxf(dts * A, -10000.0f);
        float x2 = x * x, x3 = x2 * x, x4 = x3 * x, x5 = x4 * x;
        float e  = 1.0f + x + x2 / 2.0f + x3 / 6.0f + x4 / 24.0f + x5 / 120.0f;
        e = fminf(fmaxf(e, 0.0f), 1.0f);
        g_dtv[b * NHEADS + t] = dts;
        g_scl[b * NHEADS + t] = e;
    }
}

// ---------------- K3: state readout (HBM-bound; state read exactly once) ----------------
__global__ void state_kernel(const float* __restrict__ S) {
    int warp = threadIdx.x >> 5, lane = threadIdx.x & 31;
    int wg = blockIdx.x * (blockDim.x >> 5) + warp;  // 0..65535
    int pg = wg & 15;
    int h  = (wg >> 4) & 63;
    int b  = wg >> 10;

    float4 C4 = ((const float4*)(g_Cq + b * DSTATE))[lane];
    const float* Sb = S + (((size_t)b * NHEADS + h) * HEADDIM + pg * 4) * DSTATE;

    float p[4];
    #pragma unroll
    for (int i = 0; i < 4; i++) {
        float4 s4 = ((const float4*)(Sb + i * DSTATE))[lane];
        p[i] = s4.x * C4.x + s4.y * C4.y + s4.z * C4.z + s4.w * C4.w;
    }
    #pragma unroll
    for (int o = 16; o; o >>= 1) {
        #pragma unroll
        for (int i = 0; i < 4; i++) p[i] += __shfl_xor_sync(0xFFFFFFFFu, p[i], o);
    }
    if (lane < 4) {
        float sv = 0.f;
        #pragma unroll
        for (int i = 0; i < 4; i++) if (lane == i) sv = p[i];
        int   pp  = pg * 4 + lane;
        float sc  = g_scl[b * NHEADS + h];
        float dtv = g_dtv[b * NHEADS + h];
        float bcd = g_bcd[b];
        float xv  = g_xfq[b * DSSM + h * HEADDIM + pp];
        g_yraw[b * DSSM + h * HEADDIM + pp] = sc * sv + dtv * bcd * xv;
    }
}

// ---------------- K4: gated epilogue + double fake-quant -> int8 y ----------------
__global__ void k4_kernel(const float* __restrict__ Dp) {
    __shared__ float sh[256];
    __shared__ __align__(16) float shy[DSSM];
    __shared__ float s_s1, s_s2;
    int b = blockIdx.x, t = threadIdx.x;
    const float* yr = g_yraw + b * DSSM;

    float m = 0.f;
    for (int i = t; i < DSSM; i += 256) m = fmaxf(m, fabsf(yr[i]));
    sh[t] = m; __syncthreads();
    for (int s = 128; s > 0; s >>= 1) { if (t < s) sh[t] = fmaxf(sh[t], sh[t + s]); __syncthreads(); }
    if (t == 0) { float s1 = sh[0] / 127.0f; s_s1 = (s1 == 0.f) ? 1.f : s1; }
    __syncthreads();
    float s1 = s_s1;

    float m2 = 0.f;
    for (int i = t; i < DSSM; i += 256) {
        float yq1 = rintf(yr[i] / s1) * s1;                    // fake_quant(y)
        float z   = g_zx[b * DINPROJ + i];
        float y2  = (yq1 + Dp[i] * g_xfq[b * DSSM + i]) * fmaxf(z, 0.f);
        shy[i] = y2;
        m2 = fmaxf(m2, fabsf(y2));
    }
    sh[t] = m2; __syncthreads();
    for (int s = 128; s > 0; s >>= 1) { if (t < s) sh[t] = fmaxf(sh[t], sh[t + s]); __syncthreads(); }
    if (t == 0) { float s2 = sh[0] / 127.0f; s_s2 = (s2 == 0.f) ? 1.f : s2; }
    __syncthreads();
    float s2 = s_s2;
    // final effective scale after the 3rd fake_quant inside quant_linear
    if (t == 0) g_ys[b] = (127.0f * s2) / 127.0f;

    const float4* shy4 = (const float4*)shy;
    for (int k4 = t; k4 < 1024; k4 += 256) {
        float4 v = shy4[k4];
        g_yq[b * 1024 + k4] = pack4(v.x, v.y, v.z, v.w, s2);
    }
}

// ---------------- launch ----------------
extern "C" void kernel_launch(void* const* d_in, const int* in_sizes, int n_in,
                              void* d_out, int out_size) {
    (void)in_sizes; (void)n_in; (void)out_size;
    const float* hs   = (const float*)d_in[0];
    const float* ssm  = (const float*)d_in[1];
    const float* Win  = (const float*)d_in[2];
    const float* dtb  = (const float*)d_in[3];
    const float* Alog = (const float*)d_in[4];
    const float* Dp   = (const float*)d_in[5];
    const float* Wout = (const float*)d_in[6];
    float* out = (float*)d_out;

    void *p_xq, *p_xs, *p_wq1, *p_ws1, *p_zx, *p_yq, *p_ys, *p_wq2, *p_ws2;
    cudaGetSymbolAddress(&p_xq,  g_xq);
    cudaGetSymbolAddress(&p_xs,  g_xs);
    cudaGetSymbolAddress(&p_wq1, g_wq1);
    cudaGetSymbolAddress(&p_ws1, g_ws1);
    cudaGetSymbolAddress(&p_zx,  g_zx);
    cudaGetSymbolAddress(&p_yq,  g_yq);
    cudaGetSymbolAddress(&p_ys,  g_ys);
    cudaGetSymbolAddress(&p_wq2, g_wq2);
    cudaGetSymbolAddress(&p_ws2, g_ws2);

    quant_x_kernel<<<NB, 256>>>(hs);
    quant_w_kernel<16><<<DINPROJ / 8, 256>>>(Win, (int*)p_wq1, (float*)p_ws1);
    gemm_kernel<8, 16><<<DINPROJ / 32, 128>>>((const int*)p_wq1, (const float*)p_ws1,
                                              (const int*)p_xq,  (const float*)p_xs,
                                              (float*)p_zx, DINPROJ);
    k2_kernel<<<NB, 256>>>(dtb, Alog);
    state_kernel<<<(NB * NHEADS * 16) / 8, 256>>>(ssm);
    k4_kernel<<<NB, 256>>>(Dp);
    quant_w_kernel<32><<<DMODEL / 8, 256>>>(Wout, (int*)p_wq2, (float*)p_ws2);
    gemm_kernel<4, 32><<<DMODEL / 8, 64>>>((const int*)p_wq2, (const float*)p_ws2,
                                           (const int*)p_yq,  (const float*)p_ys,
                                           out, DMODEL);
}